// round 10
// baseline (speedup 1.0000x reference)
#include <cuda_runtime.h>

#define NN 100000   // nodes
#define NPAD 100096 // padded node count (391 blocks * 256)
#define NE 500000   // edges
#define NH 4        // heads
#define HD 32       // output width
#define PROJ 128
#define U16 16      // folded edge-feature width

// folded-parameter layout inside g_fold (floats)
#define A_OFF     0            // 4*3*3 = 36  quadratic form (pre-scaled 1/sqrt(32))
#define LIN_OFF   36           // 4*3  = 12
#define S0_OFF    48           // 4
#define SCORE_SZ  52
#define B_OFF     52           // 16*32 = 512
#define BOUT_OFF  564          // 32
#define GAMMA_OFF 596          // 32
#define BETA_OFF  628          // 32
#define FOLD_SZ   660

// ---------------- device scratch (no allocations allowed) ----------------
__device__ __align__(16) float g_seg[NPAD * U16]; // zeroed by pack_setup each launch
__device__ __align__(16) float4 g_pos4[NN];       // padded positions for 1-LDG gathers
__device__ __align__(16) float g_fold[FOLD_SZ];   // folded params
__device__ int   g_is64;                          // edge_index dtype flag

// ---------------- kernel 1: zero seg + pack positions + weight fold ----------------
__global__ void __launch_bounds__(256) pack_setup_kernel(
        const float* __restrict__ pos,
        const int* __restrict__ eraw,
        const float* __restrict__ Wq, const float* __restrict__ bq,
        const float* __restrict__ Wk, const float* __restrict__ bk,
        const float* __restrict__ Wv, const float* __restrict__ bv,
        const float* __restrict__ Wout, const float* __restrict__ bout,
        const float* __restrict__ gamma, const float* __restrict__ beta) {
    const int gid = blockIdx.x * blockDim.x + threadIdx.x;
    const int gsz = gridDim.x * blockDim.x;

    // zero the accumulator (grid-stride, v4) — covers padded rows too
    float4* s4 = reinterpret_cast<float4*>(g_seg);
    const int n4 = NPAD * U16 / 4;
    const float4 z = make_float4(0.f, 0.f, 0.f, 0.f);
    for (int j = gid; j < n4; j += gsz) s4[j] = z;

    // pack positions into float4
    for (int j = gid; j < NN; j += gsz)
        g_pos4[j] = make_float4(__ldg(&pos[j * 3 + 0]),
                                __ldg(&pos[j * 3 + 1]),
                                __ldg(&pos[j * 3 + 2]), 0.f);

    const int t = threadIdx.x;
    const float inv = 0.17677669529663687f;  // 1/sqrt(32)

    if (blockIdx.x < 2) {
        // ---- B fold: one thread per output, lane = o (coalesced Wout rows) ----
        int idx = blockIdx.x * 256 + t;           // 0..511
        int j = idx >> 5, o = idx & 31;
        int h = j >> 2, ii = j & 3;
        const float* wsrc = (ii < 3) ? &Wv[ii * PROJ + h * HD] : &bv[h * HD];
        const float* wo   = &Wout[(size_t)h * HD * HD + o];
        float acc[8];
#pragma unroll
        for (int k = 0; k < 8; k++) acc[k] = 0.f;
#pragma unroll
        for (int d = 0; d < HD; d += 8) {
#pragma unroll
            for (int k = 0; k < 8; k++)
                acc[k] = fmaf(__ldg(&wsrc[d + k]), __ldg(&wo[(d + k) * HD]), acc[k]);
        }
        g_fold[B_OFF + idx] = ((acc[0] + acc[1]) + (acc[2] + acc[3]))
                            + ((acc[4] + acc[5]) + (acc[6] + acc[7]));
    } else if (blockIdx.x == 2) {
        if (t < NH * 9) {
            int h = t / 9, ii = (t % 9) / 3, jj = t % 3;
            const float* wq = &Wq[ii * PROJ + h * HD];
            const float* wk = &Wk[jj * PROJ + h * HD];
            float acc[8];
#pragma unroll
            for (int k = 0; k < 8; k++) acc[k] = 0.f;
#pragma unroll
            for (int d = 0; d < HD; d += 8) {
#pragma unroll
                for (int k = 0; k < 8; k++)
                    acc[k] = fmaf(__ldg(&wq[d + k]), __ldg(&wk[d + k]), acc[k]);
            }
            g_fold[A_OFF + t] = (((acc[0] + acc[1]) + (acc[2] + acc[3]))
                               + ((acc[4] + acc[5]) + (acc[6] + acc[7]))) * inv;
        } else if (t < 48) {
            int idx = t - 36;
            int h = idx / 3, ii = idx % 3;
            const float* wq = &Wq[ii * PROJ + h * HD];
            const float* wk = &Wk[ii * PROJ + h * HD];
            const float* bqv = &bq[h * HD];
            const float* bkv = &bk[h * HD];
            float a0 = 0.f, a1 = 0.f, a2 = 0.f, a3 = 0.f;
#pragma unroll
            for (int d = 0; d < HD; d += 2) {
                a0 = fmaf(__ldg(&wq[d]),     __ldg(&bkv[d]),     a0);
                a1 = fmaf(__ldg(&wk[d]),     __ldg(&bqv[d]),     a1);
                a2 = fmaf(__ldg(&wq[d + 1]), __ldg(&bkv[d + 1]), a2);
                a3 = fmaf(__ldg(&wk[d + 1]), __ldg(&bqv[d + 1]), a3);
            }
            g_fold[LIN_OFF + idx] = ((a0 + a1) + (a2 + a3)) * inv;
        } else if (t < 52) {
            int h = t - 48;
            const float* bqv = &bq[h * HD];
            const float* bkv = &bk[h * HD];
            float a0 = 0.f, a1 = 0.f;
#pragma unroll
            for (int d = 0; d < HD; d += 2) {
                a0 = fmaf(__ldg(&bqv[d]),     __ldg(&bkv[d]),     a0);
                a1 = fmaf(__ldg(&bqv[d + 1]), __ldg(&bkv[d + 1]), a1);
            }
            g_fold[S0_OFF + h] = (a0 + a1) * inv;
        } else if (t >= 64 && t < 160) {
            int idx = t - 64;
            const float* src = (idx < HD) ? &bout[idx]
                             : (idx < 2 * HD) ? &gamma[idx - HD]
                             : &beta[idx - 2 * HD];
            g_fold[BOUT_OFF + idx] = __ldg(src);
        } else if (t == 192) {
            // int64 edge_index: node ids < 1e5 -> every odd 32-bit word is 0.
            int acc = 0;
#pragma unroll
            for (int k = 0; k < 32; k++) acc |= __ldg(&eraw[2 * k + 1]);
            g_is64 = (acc == 0);
        }
    }
}

// ---------------- kernel 2: per-edge scores + 16-wide scatter (2 edges/thread) ----------------
__device__ __forceinline__ void red_add_v4(float* p, float4 v) {
    asm volatile("red.global.add.v4.f32 [%0], {%1,%2,%3,%4};"
                 :: "l"(p), "f"(v.x), "f"(v.y), "f"(v.z), "f"(v.w)
                 : "memory");
}

__device__ __forceinline__ void edge_compute(const float* sp, int col, float4 pr, float4 pc) {
    float r[3] = { pr.x - pc.x, pr.y - pc.y, pr.z - pc.z };
    float s[NH];
    float mx = -1e30f;
#pragma unroll
    for (int h = 0; h < NH; h++) {
        float acc = sp[S0_OFF + h];
#pragma unroll
        for (int i = 0; i < 3; i++) {
            float t = sp[LIN_OFF + h * 3 + i];
#pragma unroll
            for (int j = 0; j < 3; j++)
                t = fmaf(sp[A_OFF + h * 9 + i * 3 + j], r[j], t);
            acc = fmaf(r[i], t, acc);
        }
        s[h] = acc;
        mx = fmaxf(mx, acc);
    }
    float a[NH], den = 0.f;
#pragma unroll
    for (int h = 0; h < NH; h++) { a[h] = __expf(s[h] - mx); den += a[h]; }
    float dinv = 1.0f / den;

    float* base = &g_seg[(size_t)col * U16];
#pragma unroll
    for (int h = 0; h < NH; h++) {
        float ah = a[h] * dinv;
        red_add_v4(base + h * 4, make_float4(ah * r[0], ah * r[1], ah * r[2], ah));
    }
}

__global__ void __launch_bounds__(256) edge_kernel(const int* __restrict__ eraw) {
    __shared__ float sp[SCORE_SZ];
    if (threadIdx.x < SCORE_SZ) sp[threadIdx.x] = g_fold[threadIdx.x];
    __syncthreads();

    int e0 = (blockIdx.x * blockDim.x + threadIdx.x) * 2;
    if (e0 >= NE) return;

    int row0, col0, row1, col1;
    if (g_is64) {
        const longlong2* pr = reinterpret_cast<const longlong2*>(eraw);
        longlong2 rw = __ldg(&pr[e0 >> 1]);            // rows e0, e0+1
        longlong2 cl = __ldg(&pr[(NE + e0) >> 1]);     // cols e0, e0+1
        row0 = (int)rw.x; row1 = (int)rw.y;
        col0 = (int)cl.x; col1 = (int)cl.y;
    } else {
        const int2* pi = reinterpret_cast<const int2*>(eraw);
        int2 rw = __ldg(&pi[e0 >> 1]);
        int2 cl = __ldg(&pi[(NE + e0) >> 1]);
        row0 = rw.x; row1 = rw.y;
        col0 = cl.x; col1 = cl.y;
    }

    float4 pr0 = g_pos4[row0];
    float4 pc0 = g_pos4[col0];
    float4 pr1 = g_pos4[row1];
    float4 pc1 = g_pos4[col1];

    edge_compute(sp, col0, pr0, pc0);
    edge_compute(sp, col1, pr1, pc1);
}

// ---------------- kernel 3: warp-transposed node epilogue (lane = output ch) ----------------
// Block = 256 threads handles 256 nodes. Each warp owns 32 nodes, processed 2 at
// a time; within a node all 32 lanes cooperate (lane = output channel o).
__global__ void __launch_bounds__(256) node_kernel(float* __restrict__ out) {
    __shared__ __align__(16) float4 sU[256 * 4];   // 256 nodes * 16 floats = 16KB

    const int tid  = threadIdx.x;
    const int warp = tid >> 5;
    const int lane = tid & 31;
    const int nbase = blockIdx.x * 256;

    // stage this block's u-tile (coalesced; g_seg padded to NPAD rows)
    const float4* g4 = reinterpret_cast<const float4*>(g_seg);
    const int base4 = nbase * 4;
#pragma unroll
    for (int k = 0; k < 4; k++)
        sU[k * 256 + tid] = g4[base4 + k * 256 + tid];
    __syncthreads();

    // per-lane constants (lane = output channel)
    float bj[U16];
#pragma unroll
    for (int j = 0; j < U16; j++) bj[j] = g_fold[B_OFF + j * HD + lane];
    const float bo = g_fold[BOUT_OFF + lane];
    const float ga = g_fold[GAMMA_OFF + lane];
    const float be = g_fold[BETA_OFF + lane];

    // NN % 32 == 0 -> warp validity is uniform
    if (nbase + warp * 32 >= NN) return;
    const unsigned mask = 0xffffffffu;

    for (int m = 0; m < 32; m += 2) {
        const int l0 = warp * 32 + m;
        // broadcast LDS.128 of both nodes' u vectors
        float4 ua = sU[l0 * 4 + 0], ub = sU[l0 * 4 + 1],
               uc = sU[l0 * 4 + 2], ud = sU[l0 * 4 + 3];
        float4 va = sU[l0 * 4 + 4], vb = sU[l0 * 4 + 5],
               vc = sU[l0 * 4 + 6], vd = sU[l0 * 4 + 7];

        float rinv0 = 1.0f / fmaxf(ua.w + ub.w + uc.w + ud.w, 1.0f);
        float rinv1 = 1.0f / fmaxf(va.w + vb.w + vc.w + vd.w, 1.0f);

        // y = u @ B   (B column 'lane' in registers)
        float y0 = ua.x * bj[0], y1 = va.x * bj[0];
        y0 = fmaf(ua.y, bj[1],  y0); y1 = fmaf(va.y, bj[1],  y1);
        y0 = fmaf(ua.z, bj[2],  y0); y1 = fmaf(va.z, bj[2],  y1);
        y0 = fmaf(ua.w, bj[3],  y0); y1 = fmaf(va.w, bj[3],  y1);
        y0 = fmaf(ub.x, bj[4],  y0); y1 = fmaf(vb.x, bj[4],  y1);
        y0 = fmaf(ub.y, bj[5],  y0); y1 = fmaf(vb.y, bj[5],  y1);
        y0 = fmaf(ub.z, bj[6],  y0); y1 = fmaf(vb.z, bj[6],  y1);
        y0 = fmaf(ub.w, bj[7],  y0); y1 = fmaf(vb.w, bj[7],  y1);
        y0 = fmaf(uc.x, bj[8],  y0); y1 = fmaf(vc.x, bj[8],  y1);
        y0 = fmaf(uc.y, bj[9],  y0); y1 = fmaf(vc.y, bj[9],  y1);
        y0 = fmaf(uc.z, bj[10], y0); y1 = fmaf(vc.z, bj[10], y1);
        y0 = fmaf(uc.w, bj[11], y0); y1 = fmaf(vc.w, bj[11], y1);
        y0 = fmaf(ud.x, bj[12], y0); y1 = fmaf(vd.x, bj[12], y1);
        y0 = fmaf(ud.y, bj[13], y0); y1 = fmaf(vd.y, bj[13], y1);
        y0 = fmaf(ud.z, bj[14], y0); y1 = fmaf(vd.z, bj[14], y1);
        y0 = fmaf(ud.w, bj[15], y0); y1 = fmaf(vd.w, bj[15], y1);

        y0 = fmaf(y0, rinv0, bo);
        y1 = fmaf(y1, rinv1, bo);

        // LayerNorm across the warp (32 channels), both nodes interleaved
        float s0 = y0, s1 = y1;
#pragma unroll
        for (int o = 16; o > 0; o >>= 1) {
            s0 += __shfl_xor_sync(mask, s0, o);
            s1 += __shfl_xor_sync(mask, s1, o);
        }
        float mu0 = s0 * (1.0f / 32.0f);
        float mu1 = s1 * (1.0f / 32.0f);
        float d0 = y0 - mu0, d1 = y1 - mu1;
        float q0 = d0 * d0, q1 = d1 * d1;
#pragma unroll
        for (int o = 16; o > 0; o >>= 1) {
            q0 += __shfl_xor_sync(mask, q0, o);
            q1 += __shfl_xor_sync(mask, q1, o);
        }
        float sf0 = rsqrtf(q0 * (1.0f / 32.0f) + 1e-5f);
        float sf1 = rsqrtf(q1 * (1.0f / 32.0f) + 1e-5f);

        float x0 = d0 * sf0 * ga + be;
        float x1 = d1 * sf1 * ga + be;
        x0 = x0 / (1.0f + __expf(-x0));   // SiLU
        x1 = x1 / (1.0f + __expf(-x1));

        out[(size_t)(nbase + l0) * HD + lane]     = x0;   // coalesced per warp
        out[(size_t)(nbase + l0 + 1) * HD + lane] = x1;
    }
}

// ---------------- launch ----------------
extern "C" void kernel_launch(void* const* d_in, const int* in_sizes, int n_in,
                              void* d_out, int out_size) {
    const float* pos   = (const float*)d_in[0];
    const int*   edge  = (const int*)d_in[1];
    const float* Wq    = (const float*)d_in[2];
    const float* bq    = (const float*)d_in[3];
    const float* Wk    = (const float*)d_in[4];
    const float* bk    = (const float*)d_in[5];
    const float* Wv    = (const float*)d_in[6];
    const float* bv    = (const float*)d_in[7];
    const float* Wout  = (const float*)d_in[8];
    const float* bout  = (const float*)d_in[9];
    const float* gamma = (const float*)d_in[10];
    const float* beta  = (const float*)d_in[11];
    float* out = (float*)d_out;

    pack_setup_kernel<<<608, 256>>>(pos, edge, Wq, bq, Wk, bk, Wv, bv,
                                    Wout, bout, gamma, beta);
    edge_kernel<<<(NE / 2 + 255) / 256, 256>>>(edge);
    node_kernel<<<(NN + 255) / 256, 256>>>(out);
}

// round 11
// speedup vs baseline: 1.0344x; 1.0344x over previous
#include <cuda_runtime.h>

#define NN 100000   // nodes
#define NPAD 100096 // padded node count
#define NE 500000   // edges
#define NH 4        // heads
#define HD 32       // output width
#define PROJ 128
#define U16 16      // folded edge-feature width

// folded-parameter layout inside g_fold (floats)
#define A_OFF     0            // 4*3*3 = 36  quadratic form (pre-scaled 1/sqrt(32))
#define LIN_OFF   36           // 4*3  = 12
#define S0_OFF    48           // 4
#define SCORE_SZ  52
#define B_OFF     52           // 16*32 = 512
#define BOUT_OFF  564          // 32
#define GAMMA_OFF 596          // 32
#define BETA_OFF  628          // 32
#define FOLD_SZ   660

// ---------------- device scratch (no allocations allowed) ----------------
__device__ __align__(16) float g_seg[NPAD * U16]; // zeroed by pack_setup each launch
__device__ __align__(16) float4 g_pos4[NN];       // padded positions for 1-LDG gathers
__device__ __align__(16) float g_fold[FOLD_SZ];   // folded params
__device__ int   g_is64;                          // edge_index dtype flag

// ---------------- kernel 1: zero seg + pack positions + weight fold ----------------
__global__ void __launch_bounds__(256) pack_setup_kernel(
        const float* __restrict__ pos,
        const int* __restrict__ eraw,
        const float* __restrict__ Wq, const float* __restrict__ bq,
        const float* __restrict__ Wk, const float* __restrict__ bk,
        const float* __restrict__ Wv, const float* __restrict__ bv,
        const float* __restrict__ Wout, const float* __restrict__ bout,
        const float* __restrict__ gamma, const float* __restrict__ beta) {
    const int gid = blockIdx.x * blockDim.x + threadIdx.x;
    const int gsz = gridDim.x * blockDim.x;

    // zero the accumulator (grid-stride, v4) — covers padded rows too
    float4* s4 = reinterpret_cast<float4*>(g_seg);
    const int n4 = NPAD * U16 / 4;
    const float4 z = make_float4(0.f, 0.f, 0.f, 0.f);
    for (int j = gid; j < n4; j += gsz) s4[j] = z;

    // pack positions into float4
    for (int j = gid; j < NN; j += gsz)
        g_pos4[j] = make_float4(__ldg(&pos[j * 3 + 0]),
                                __ldg(&pos[j * 3 + 1]),
                                __ldg(&pos[j * 3 + 2]), 0.f);

    const int t = threadIdx.x;
    const float inv = 0.17677669529663687f;  // 1/sqrt(32)

    if (blockIdx.x < 2) {
        // ---- B fold: one thread per output, lane = o (coalesced Wout rows) ----
        int idx = blockIdx.x * 256 + t;           // 0..511
        int j = idx >> 5, o = idx & 31;
        int h = j >> 2, ii = j & 3;
        const float* wsrc = (ii < 3) ? &Wv[ii * PROJ + h * HD] : &bv[h * HD];
        const float* wo   = &Wout[(size_t)h * HD * HD + o];
        float acc[8];
#pragma unroll
        for (int k = 0; k < 8; k++) acc[k] = 0.f;
#pragma unroll
        for (int d = 0; d < HD; d += 8) {
#pragma unroll
            for (int k = 0; k < 8; k++)
                acc[k] = fmaf(__ldg(&wsrc[d + k]), __ldg(&wo[(d + k) * HD]), acc[k]);
        }
        g_fold[B_OFF + idx] = ((acc[0] + acc[1]) + (acc[2] + acc[3]))
                            + ((acc[4] + acc[5]) + (acc[6] + acc[7]));
    } else if (blockIdx.x == 2) {
        if (t < NH * 9) {
            int h = t / 9, ii = (t % 9) / 3, jj = t % 3;
            const float* wq = &Wq[ii * PROJ + h * HD];
            const float* wk = &Wk[jj * PROJ + h * HD];
            float acc[8];
#pragma unroll
            for (int k = 0; k < 8; k++) acc[k] = 0.f;
#pragma unroll
            for (int d = 0; d < HD; d += 8) {
#pragma unroll
                for (int k = 0; k < 8; k++)
                    acc[k] = fmaf(__ldg(&wq[d + k]), __ldg(&wk[d + k]), acc[k]);
            }
            g_fold[A_OFF + t] = (((acc[0] + acc[1]) + (acc[2] + acc[3]))
                               + ((acc[4] + acc[5]) + (acc[6] + acc[7]))) * inv;
        } else if (t < 48) {
            int idx = t - 36;
            int h = idx / 3, ii = idx % 3;
            const float* wq = &Wq[ii * PROJ + h * HD];
            const float* wk = &Wk[ii * PROJ + h * HD];
            const float* bqv = &bq[h * HD];
            const float* bkv = &bk[h * HD];
            float a0 = 0.f, a1 = 0.f, a2 = 0.f, a3 = 0.f;
#pragma unroll
            for (int d = 0; d < HD; d += 2) {
                a0 = fmaf(__ldg(&wq[d]),     __ldg(&bkv[d]),     a0);
                a1 = fmaf(__ldg(&wk[d]),     __ldg(&bqv[d]),     a1);
                a2 = fmaf(__ldg(&wq[d + 1]), __ldg(&bkv[d + 1]), a2);
                a3 = fmaf(__ldg(&wk[d + 1]), __ldg(&bqv[d + 1]), a3);
            }
            g_fold[LIN_OFF + idx] = ((a0 + a1) + (a2 + a3)) * inv;
        } else if (t < 52) {
            int h = t - 48;
            const float* bqv = &bq[h * HD];
            const float* bkv = &bk[h * HD];
            float a0 = 0.f, a1 = 0.f;
#pragma unroll
            for (int d = 0; d < HD; d += 2) {
                a0 = fmaf(__ldg(&bqv[d]),     __ldg(&bkv[d]),     a0);
                a1 = fmaf(__ldg(&bqv[d + 1]), __ldg(&bkv[d + 1]), a1);
            }
            g_fold[S0_OFF + h] = (a0 + a1) * inv;
        } else if (t >= 64 && t < 160) {
            int idx = t - 64;
            const float* src = (idx < HD) ? &bout[idx]
                             : (idx < 2 * HD) ? &gamma[idx - HD]
                             : &beta[idx - 2 * HD];
            g_fold[BOUT_OFF + idx] = __ldg(src);
        } else if (t == 192) {
            // int64 edge_index: node ids < 1e5 -> every odd 32-bit word is 0.
            int acc = 0;
#pragma unroll
            for (int k = 0; k < 32; k++) acc |= __ldg(&eraw[2 * k + 1]);
            g_is64 = (acc == 0);
        }
    }
}

// ---------------- kernel 2: per-edge scores + 16-wide scatter (2 edges/thread) ----------------
__device__ __forceinline__ void red_add_v4(float* p, float4 v) {
    asm volatile("red.global.add.v4.f32 [%0], {%1,%2,%3,%4};"
                 :: "l"(p), "f"(v.x), "f"(v.y), "f"(v.z), "f"(v.w)
                 : "memory");
}

__device__ __forceinline__ void edge_compute(const float* sp, int col, float4 pr, float4 pc) {
    float r[3] = { pr.x - pc.x, pr.y - pc.y, pr.z - pc.z };
    float s[NH];
    float mx = -1e30f;
#pragma unroll
    for (int h = 0; h < NH; h++) {
        float acc = sp[S0_OFF + h];
#pragma unroll
        for (int i = 0; i < 3; i++) {
            float t = sp[LIN_OFF + h * 3 + i];
#pragma unroll
            for (int j = 0; j < 3; j++)
                t = fmaf(sp[A_OFF + h * 9 + i * 3 + j], r[j], t);
            acc = fmaf(r[i], t, acc);
        }
        s[h] = acc;
        mx = fmaxf(mx, acc);
    }
    float a[NH], den = 0.f;
#pragma unroll
    for (int h = 0; h < NH; h++) { a[h] = __expf(s[h] - mx); den += a[h]; }
    float dinv = 1.0f / den;

    float* base = &g_seg[(size_t)col * U16];
#pragma unroll
    for (int h = 0; h < NH; h++) {
        float ah = a[h] * dinv;
        red_add_v4(base + h * 4, make_float4(ah * r[0], ah * r[1], ah * r[2], ah));
    }
}

__global__ void __launch_bounds__(256) edge_kernel(const int* __restrict__ eraw) {
    __shared__ float sp[SCORE_SZ];
    if (threadIdx.x < SCORE_SZ) sp[threadIdx.x] = g_fold[threadIdx.x];
    __syncthreads();

    int e0 = (blockIdx.x * blockDim.x + threadIdx.x) * 2;
    if (e0 >= NE) return;

    int row0, col0, row1, col1;
    if (g_is64) {
        const longlong2* pr = reinterpret_cast<const longlong2*>(eraw);
        longlong2 rw = __ldg(&pr[e0 >> 1]);            // rows e0, e0+1
        longlong2 cl = __ldg(&pr[(NE + e0) >> 1]);     // cols e0, e0+1
        row0 = (int)rw.x; row1 = (int)rw.y;
        col0 = (int)cl.x; col1 = (int)cl.y;
    } else {
        const int2* pi = reinterpret_cast<const int2*>(eraw);
        int2 rw = __ldg(&pi[e0 >> 1]);
        int2 cl = __ldg(&pi[(NE + e0) >> 1]);
        row0 = rw.x; row1 = rw.y;
        col0 = cl.x; col1 = cl.y;
    }

    float4 pr0 = g_pos4[row0];
    float4 pc0 = g_pos4[col0];
    float4 pr1 = g_pos4[row1];
    float4 pc1 = g_pos4[col1];

    edge_compute(sp, col0, pr0, pc0);
    edge_compute(sp, col1, pr1, pc1);
}

// ---------------- kernel 3: per-node u@B + LN + SiLU (quad-sub, 4 nodes/thread) ----------------
__global__ void __launch_bounds__(256) node_kernel(float* __restrict__ out) {
    __shared__ __align__(16) float sB[U16 * HD];   // 512 floats
    __shared__ __align__(16) float sEpi[3 * HD];   // bout | gamma | beta

    for (int i = threadIdx.x; i < U16 * HD; i += 256) sB[i] = g_fold[B_OFF + i];
    for (int i = threadIdx.x; i < 3 * HD; i += 256)  sEpi[i] = g_fold[BOUT_OFF + i];
    __syncthreads();

    int gt    = blockIdx.x * blockDim.x + threadIdx.x;
    int group = gt >> 2;          // 4-node group
    int sub   = gt & 3;           // which 8-output slice
    int n0    = group * 4;        // n0..n0+3 (reads safe: g_seg padded+zeroed to NPAD)
    const unsigned mask = 0xffffffffu;

    // load u for 4 nodes (quad-sibling reads coalesce/broadcast in L1)
    float s[4][U16];
#pragma unroll
    for (int m = 0; m < 4; m++) {
        const float4* p = reinterpret_cast<const float4*>(&g_seg[(size_t)(n0 + m) * U16]);
#pragma unroll
        for (int k = 0; k < 4; k++) {
            float4 v = p[k];
            s[m][k*4+0]=v.x; s[m][k*4+1]=v.y; s[m][k*4+2]=v.z; s[m][k*4+3]=v.w;
        }
    }

    float rinv[4];
#pragma unroll
    for (int m = 0; m < 4; m++)
        rinv[m] = 1.0f / fmaxf(s[m][3] + s[m][7] + s[m][11] + s[m][15], 1.0f);

    // y[m] = s[m] @ B slice ; one B read serves 4 nodes
    const int o0 = sub * 8;
    float y[4][8];
#pragma unroll
    for (int m = 0; m < 4; m++)
#pragma unroll
        for (int c = 0; c < 8; c++) y[m][c] = 0.f;

#pragma unroll
    for (int j = 0; j < U16; j++) {
        const float4* brow = reinterpret_cast<const float4*>(&sB[j * HD + o0]);
        float4 b0 = brow[0], b1 = brow[1];
#pragma unroll
        for (int m = 0; m < 4; m++) {
            float a = s[m][j];
            y[m][0]=fmaf(a,b0.x,y[m][0]); y[m][1]=fmaf(a,b0.y,y[m][1]);
            y[m][2]=fmaf(a,b0.z,y[m][2]); y[m][3]=fmaf(a,b0.w,y[m][3]);
            y[m][4]=fmaf(a,b1.x,y[m][4]); y[m][5]=fmaf(a,b1.y,y[m][5]);
            y[m][6]=fmaf(a,b1.z,y[m][6]); y[m][7]=fmaf(a,b1.w,y[m][7]);
        }
    }

    float sum[4] = {0.f, 0.f, 0.f, 0.f};
#pragma unroll
    for (int m = 0; m < 4; m++)
#pragma unroll
        for (int c = 0; c < 8; c++) {
            y[m][c] = fmaf(y[m][c], rinv[m], sEpi[o0 + c]);
            sum[m] += y[m][c];
        }
#pragma unroll
    for (int m = 0; m < 4; m++) {
        sum[m] += __shfl_xor_sync(mask, sum[m], 1);
        sum[m] += __shfl_xor_sync(mask, sum[m], 2);
    }
    float mu[4], sq[4] = {0.f, 0.f, 0.f, 0.f};
#pragma unroll
    for (int m = 0; m < 4; m++) mu[m] = sum[m] * (1.0f / 32.0f);
#pragma unroll
    for (int m = 0; m < 4; m++)
#pragma unroll
        for (int c = 0; c < 8; c++) {
            float d = y[m][c] - mu[m];
            sq[m] = fmaf(d, d, sq[m]);
        }
#pragma unroll
    for (int m = 0; m < 4; m++) {
        sq[m] += __shfl_xor_sync(mask, sq[m], 1);
        sq[m] += __shfl_xor_sync(mask, sq[m], 2);
    }

    if (n0 >= NN) return;   // tail threads (reads were padded); NN%4==0 so group all-valid

#pragma unroll
    for (int m = 0; m < 4; m++) {
        float sf = rsqrtf(sq[m] * (1.0f / 32.0f) + 1e-5f);
        float4* op = reinterpret_cast<float4*>(&out[(size_t)(n0 + m) * HD + o0]);
#pragma unroll
        for (int k = 0; k < 2; k++) {
            float4 v;
            float* vp = &v.x;
#pragma unroll
            for (int c = 0; c < 4; c++) {
                int o = o0 + k * 4 + c;
                float x = (y[m][k*4+c] - mu[m]) * sf * sEpi[HD + o] + sEpi[2 * HD + o];
                vp[c] = x / (1.0f + __expf(-x));   // SiLU
            }
            op[k] = v;
        }
    }
}

// ---------------- launch ----------------
extern "C" void kernel_launch(void* const* d_in, const int* in_sizes, int n_in,
                              void* d_out, int out_size) {
    const float* pos   = (const float*)d_in[0];
    const int*   edge  = (const int*)d_in[1];
    const float* Wq    = (const float*)d_in[2];
    const float* bq    = (const float*)d_in[3];
    const float* Wk    = (const float*)d_in[4];
    const float* bk    = (const float*)d_in[5];
    const float* Wv    = (const float*)d_in[6];
    const float* bv    = (const float*)d_in[7];
    const float* Wout  = (const float*)d_in[8];
    const float* bout  = (const float*)d_in[9];
    const float* gamma = (const float*)d_in[10];
    const float* beta  = (const float*)d_in[11];
    float* out = (float*)d_out;

    pack_setup_kernel<<<608, 256>>>(pos, edge, Wq, bq, Wk, bk, Wv, bv,
                                    Wout, bout, gamma, beta);
    edge_kernel<<<(NE / 2 + 255) / 256, 256>>>(edge);
    // one thread per (4-node group, 8-ch sub): NN/4 groups * 4 subs = NN threads
    node_kernel<<<(NN + 255) / 256, 256>>>(out);
}

// round 12
// speedup vs baseline: 1.1159x; 1.0788x over previous
#include <cuda_runtime.h>

#define NN 100000   // nodes
#define NPAD 100096 // padded node count
#define NE 500000   // edges
#define NH 4        // heads
#define HD 32       // output width
#define PROJ 128
#define U16 16      // folded edge-feature width

// folded-parameter layout inside g_fold (floats)
#define A_OFF     0            // 4*3*3 = 36  quadratic form (pre-scaled 1/sqrt(32))
#define LIN_OFF   36           // 4*3  = 12
#define S0_OFF    48           // 4
#define SCORE_SZ  52
#define B_OFF     52           // 16*32 = 512
#define BOUT_OFF  564          // 32
#define GAMMA_OFF 596          // 32
#define BETA_OFF  628          // 32
#define FOLD_SZ   660

// ---------------- device scratch (no allocations allowed) ----------------
__device__ __align__(16) float g_seg[NPAD * U16]; // zeroed by pack_setup each launch
__device__ __align__(16) float4 g_pos4[NN];       // padded positions for 1-LDG gathers
__device__ __align__(16) float g_fold[FOLD_SZ];   // folded params
__device__ int   g_is64;                          // edge_index dtype flag

// ---------------- kernel 1: zero seg + pack positions + weight fold ----------------
__global__ void __launch_bounds__(256) pack_setup_kernel(
        const float* __restrict__ pos,
        const int* __restrict__ eraw,
        const float* __restrict__ Wq, const float* __restrict__ bq,
        const float* __restrict__ Wk, const float* __restrict__ bk,
        const float* __restrict__ Wv, const float* __restrict__ bv,
        const float* __restrict__ Wout, const float* __restrict__ bout,
        const float* __restrict__ gamma, const float* __restrict__ beta) {
    const int gid = blockIdx.x * blockDim.x + threadIdx.x;
    const int gsz = gridDim.x * blockDim.x;

    // zero the accumulator (grid-stride, v4) — covers padded rows too
    float4* s4 = reinterpret_cast<float4*>(g_seg);
    const int n4 = NPAD * U16 / 4;
    const float4 z = make_float4(0.f, 0.f, 0.f, 0.f);
    for (int j = gid; j < n4; j += gsz) s4[j] = z;

    // pack positions into float4
    for (int j = gid; j < NN; j += gsz)
        g_pos4[j] = make_float4(__ldg(&pos[j * 3 + 0]),
                                __ldg(&pos[j * 3 + 1]),
                                __ldg(&pos[j * 3 + 2]), 0.f);

    const int t = threadIdx.x;
    const float inv = 0.17677669529663687f;  // 1/sqrt(32)

    if (blockIdx.x < 2) {
        // ---- B fold: one thread per output, lane = o (coalesced Wout rows) ----
        int idx = blockIdx.x * 256 + t;           // 0..511
        int j = idx >> 5, o = idx & 31;
        int h = j >> 2, ii = j & 3;
        const float* wsrc = (ii < 3) ? &Wv[ii * PROJ + h * HD] : &bv[h * HD];
        const float* wo   = &Wout[(size_t)h * HD * HD + o];
        float acc[8];
#pragma unroll
        for (int k = 0; k < 8; k++) acc[k] = 0.f;
#pragma unroll
        for (int d = 0; d < HD; d += 8) {
#pragma unroll
            for (int k = 0; k < 8; k++)
                acc[k] = fmaf(__ldg(&wsrc[d + k]), __ldg(&wo[(d + k) * HD]), acc[k]);
        }
        g_fold[B_OFF + idx] = ((acc[0] + acc[1]) + (acc[2] + acc[3]))
                            + ((acc[4] + acc[5]) + (acc[6] + acc[7]));
    } else if (blockIdx.x == 2) {
        if (t < NH * 9) {
            int h = t / 9, ii = (t % 9) / 3, jj = t % 3;
            const float* wq = &Wq[ii * PROJ + h * HD];
            const float* wk = &Wk[jj * PROJ + h * HD];
            float acc[8];
#pragma unroll
            for (int k = 0; k < 8; k++) acc[k] = 0.f;
#pragma unroll
            for (int d = 0; d < HD; d += 8) {
#pragma unroll
                for (int k = 0; k < 8; k++)
                    acc[k] = fmaf(__ldg(&wq[d + k]), __ldg(&wk[d + k]), acc[k]);
            }
            g_fold[A_OFF + t] = (((acc[0] + acc[1]) + (acc[2] + acc[3]))
                               + ((acc[4] + acc[5]) + (acc[6] + acc[7]))) * inv;
        } else if (t < 48) {
            int idx = t - 36;
            int h = idx / 3, ii = idx % 3;
            const float* wq = &Wq[ii * PROJ + h * HD];
            const float* wk = &Wk[ii * PROJ + h * HD];
            const float* bqv = &bq[h * HD];
            const float* bkv = &bk[h * HD];
            float a0 = 0.f, a1 = 0.f, a2 = 0.f, a3 = 0.f;
#pragma unroll
            for (int d = 0; d < HD; d += 2) {
                a0 = fmaf(__ldg(&wq[d]),     __ldg(&bkv[d]),     a0);
                a1 = fmaf(__ldg(&wk[d]),     __ldg(&bqv[d]),     a1);
                a2 = fmaf(__ldg(&wq[d + 1]), __ldg(&bkv[d + 1]), a2);
                a3 = fmaf(__ldg(&wk[d + 1]), __ldg(&bqv[d + 1]), a3);
            }
            g_fold[LIN_OFF + idx] = ((a0 + a1) + (a2 + a3)) * inv;
        } else if (t < 52) {
            int h = t - 48;
            const float* bqv = &bq[h * HD];
            const float* bkv = &bk[h * HD];
            float a0 = 0.f, a1 = 0.f;
#pragma unroll
            for (int d = 0; d < HD; d += 2) {
                a0 = fmaf(__ldg(&bqv[d]),     __ldg(&bkv[d]),     a0);
                a1 = fmaf(__ldg(&bqv[d + 1]), __ldg(&bkv[d + 1]), a1);
            }
            g_fold[S0_OFF + h] = (a0 + a1) * inv;
        } else if (t >= 64 && t < 160) {
            int idx = t - 64;
            const float* src = (idx < HD) ? &bout[idx]
                             : (idx < 2 * HD) ? &gamma[idx - HD]
                             : &beta[idx - 2 * HD];
            g_fold[BOUT_OFF + idx] = __ldg(src);
        } else if (t == 192) {
            // int64 edge_index: node ids < 1e5 -> every odd 32-bit word is 0.
            int acc = 0;
#pragma unroll
            for (int k = 0; k < 32; k++) acc |= __ldg(&eraw[2 * k + 1]);
            g_is64 = (acc == 0);
        }
    }
}

// ---------------- kernel 2: quad-per-edge scores + line-merged scatter ----------------
__device__ __forceinline__ void red_add_v4(float* p, float4 v) {
    asm volatile("red.global.add.v4.f32 [%0], {%1,%2,%3,%4};"
                 :: "l"(p), "f"(v.x), "f"(v.y), "f"(v.z), "f"(v.w)
                 : "memory");
}

// NE*4 = 2,000,000 threads; lane quads (aligned) own one edge, lane%4 = head.
__global__ void __launch_bounds__(256) edge_kernel(const int* __restrict__ eraw) {
    __shared__ float sp[SCORE_SZ];
    if (threadIdx.x < SCORE_SZ) sp[threadIdx.x] = g_fold[threadIdx.x];
    __syncthreads();

    const int gid = blockIdx.x * blockDim.x + threadIdx.x;
    const int e = gid >> 2;
    const int h = gid & 3;
    if (e >= NE) return;                   // NE*4 % 32 == 0 -> whole warps drop

    int row, col;
    if (g_is64) {
        const long long* p = reinterpret_cast<const long long*>(eraw);
        row = (int)__ldg(&p[e]);           // quad-same address -> merged
        col = (int)__ldg(&p[NE + e]);
    } else {
        row = __ldg(&eraw[e]);
        col = __ldg(&eraw[NE + e]);
    }

    // all 4 quad lanes load both positions; same-line lanes merge in L1tex
    float4 pr = g_pos4[row];
    float4 pc = g_pos4[col];
    const float r0 = pr.x - pc.x, r1 = pr.y - pc.y, r2 = pr.z - pc.z;

    // this lane's head score (folded quadratic form)
    const float* A = &sp[A_OFF + h * 9];
    float t0 = sp[LIN_OFF + h * 3 + 0];
    t0 = fmaf(A[0], r0, fmaf(A[1], r1, fmaf(A[2], r2, t0)));
    float t1 = sp[LIN_OFF + h * 3 + 1];
    t1 = fmaf(A[3], r0, fmaf(A[4], r1, fmaf(A[5], r2, t1)));
    float t2 = sp[LIN_OFF + h * 3 + 2];
    t2 = fmaf(A[6], r0, fmaf(A[7], r1, fmaf(A[8], r2, t2)));
    float s = fmaf(r0, t0, fmaf(r1, t1, fmaf(r2, t2, sp[S0_OFF + h])));

    // quad softmax (laneMask 1,2 stay inside aligned quads)
    const unsigned mask = 0xffffffffu;
    float mx = s;
    mx = fmaxf(mx, __shfl_xor_sync(mask, mx, 1));
    mx = fmaxf(mx, __shfl_xor_sync(mask, mx, 2));
    float a = __expf(s - mx);
    float den = a;
    den += __shfl_xor_sync(mask, den, 1);
    den += __shfl_xor_sync(mask, den, 2);
    float ah = a / den;

    // one red.v4 per lane; the quad's 4 segments = one contiguous 64B block,
    // so a warp's 32 lanes hit only 8 distinct 128B lines.
    red_add_v4(&g_seg[(size_t)col * U16 + h * 4],
               make_float4(ah * r0, ah * r1, ah * r2, ah));
}

// ---------------- kernel 3: per-node u@B + LN + SiLU (quad-sub, 2 nodes/thread) ----------------
__global__ void __launch_bounds__(256) node_kernel(float* __restrict__ out) {
    __shared__ __align__(16) float sB[U16 * HD];   // 512 floats
    __shared__ __align__(16) float sEpi[3 * HD];   // bout | gamma | beta

    for (int i = threadIdx.x; i < U16 * HD; i += 256) sB[i] = g_fold[B_OFF + i];
    for (int i = threadIdx.x; i < 3 * HD; i += 256)  sEpi[i] = g_fold[BOUT_OFF + i];
    __syncthreads();

    int gt   = blockIdx.x * blockDim.x + threadIdx.x;
    int pair = gt >> 2;
    int sub  = gt & 3;
    int n0   = pair * 2;          // NN is even -> n0, n0+1 both valid when n0 < NN
    bool valid = (n0 < NN);
    unsigned mask = 0xffffffffu;

    float s0[U16], s1[U16];
    if (valid) {
        const float4* p0 = reinterpret_cast<const float4*>(&g_seg[(size_t)n0 * U16]);
        const float4* p1 = reinterpret_cast<const float4*>(&g_seg[(size_t)(n0 + 1) * U16]);
#pragma unroll
        for (int k = 0; k < 4; k++) {
            float4 v = p0[k];
            s0[k*4+0]=v.x; s0[k*4+1]=v.y; s0[k*4+2]=v.z; s0[k*4+3]=v.w;
        }
#pragma unroll
        for (int k = 0; k < 4; k++) {
            float4 v = p1[k];
            s1[k*4+0]=v.x; s1[k*4+1]=v.y; s1[k*4+2]=v.z; s1[k*4+3]=v.w;
        }
    } else {
#pragma unroll
        for (int k = 0; k < U16; k++) { s0[k] = 0.f; s1[k] = 0.f; }
    }

    float rinv0 = 1.0f / fmaxf(s0[3] + s0[7] + s0[11] + s0[15], 1.0f);
    float rinv1 = 1.0f / fmaxf(s1[3] + s1[7] + s1[11] + s1[15], 1.0f);

    const int o0 = sub * 8;
    float y0[8], y1[8];
#pragma unroll
    for (int c = 0; c < 8; c++) { y0[c] = 0.f; y1[c] = 0.f; }
#pragma unroll
    for (int j = 0; j < U16; j++) {
        const float4* brow = reinterpret_cast<const float4*>(&sB[j * HD + o0]);
        float4 b0 = brow[0], b1 = brow[1];
        float a0 = s0[j], a1 = s1[j];
        y0[0]=fmaf(a0,b0.x,y0[0]); y0[1]=fmaf(a0,b0.y,y0[1]);
        y0[2]=fmaf(a0,b0.z,y0[2]); y0[3]=fmaf(a0,b0.w,y0[3]);
        y0[4]=fmaf(a0,b1.x,y0[4]); y0[5]=fmaf(a0,b1.y,y0[5]);
        y0[6]=fmaf(a0,b1.z,y0[6]); y0[7]=fmaf(a0,b1.w,y0[7]);
        y1[0]=fmaf(a1,b0.x,y1[0]); y1[1]=fmaf(a1,b0.y,y1[1]);
        y1[2]=fmaf(a1,b0.z,y1[2]); y1[3]=fmaf(a1,b0.w,y1[3]);
        y1[4]=fmaf(a1,b1.x,y1[4]); y1[5]=fmaf(a1,b1.y,y1[5]);
        y1[6]=fmaf(a1,b1.z,y1[6]); y1[7]=fmaf(a1,b1.w,y1[7]);
    }

    float sum0 = 0.f, sum1 = 0.f;
#pragma unroll
    for (int c = 0; c < 8; c++) {
        y0[c] = fmaf(y0[c], rinv0, sEpi[o0 + c]);
        y1[c] = fmaf(y1[c], rinv1, sEpi[o0 + c]);
        sum0 += y0[c]; sum1 += y1[c];
    }
    sum0 += __shfl_xor_sync(mask, sum0, 1);
    sum0 += __shfl_xor_sync(mask, sum0, 2);
    sum1 += __shfl_xor_sync(mask, sum1, 1);
    sum1 += __shfl_xor_sync(mask, sum1, 2);
    float mu0 = sum0 * (1.0f / 32.0f);
    float mu1 = sum1 * (1.0f / 32.0f);

    float sq0 = 0.f, sq1 = 0.f;
#pragma unroll
    for (int c = 0; c < 8; c++) {
        float d0 = y0[c] - mu0; sq0 = fmaf(d0, d0, sq0);
        float d1 = y1[c] - mu1; sq1 = fmaf(d1, d1, sq1);
    }
    sq0 += __shfl_xor_sync(mask, sq0, 1);
    sq0 += __shfl_xor_sync(mask, sq0, 2);
    sq1 += __shfl_xor_sync(mask, sq1, 1);
    sq1 += __shfl_xor_sync(mask, sq1, 2);
    float sf0 = rsqrtf(sq0 * (1.0f / 32.0f) + 1e-5f);
    float sf1 = rsqrtf(sq1 * (1.0f / 32.0f) + 1e-5f);

    if (!valid) return;

    float4* op0 = reinterpret_cast<float4*>(&out[(size_t)n0 * HD + o0]);
    float4* op1 = reinterpret_cast<float4*>(&out[(size_t)(n0 + 1) * HD + o0]);
#pragma unroll
    for (int k = 0; k < 2; k++) {
        float4 v0, v1;
        float* vp0 = &v0.x;
        float* vp1 = &v1.x;
#pragma unroll
        for (int c = 0; c < 4; c++) {
            int o = o0 + k * 4 + c;
            float g = sEpi[HD + o], bt = sEpi[2 * HD + o];
            float x0 = (y0[k*4+c] - mu0) * sf0 * g + bt;
            float x1 = (y1[k*4+c] - mu1) * sf1 * g + bt;
            vp0[c] = x0 / (1.0f + __expf(-x0));
            vp1[c] = x1 / (1.0f + __expf(-x1));
        }
        op0[k] = v0;
        op1[k] = v1;
    }
}

// ---------------- launch ----------------
extern "C" void kernel_launch(void* const* d_in, const int* in_sizes, int n_in,
                              void* d_out, int out_size) {
    const float* pos   = (const float*)d_in[0];
    const int*   edge  = (const int*)d_in[1];
    const float* Wq    = (const float*)d_in[2];
    const float* bq    = (const float*)d_in[3];
    const float* Wk    = (const float*)d_in[4];
    const float* bk    = (const float*)d_in[5];
    const float* Wv    = (const float*)d_in[6];
    const float* bv    = (const float*)d_in[7];
    const float* Wout  = (const float*)d_in[8];
    const float* bout  = (const float*)d_in[9];
    const float* gamma = (const float*)d_in[10];
    const float* beta  = (const float*)d_in[11];
    float* out = (float*)d_out;

    pack_setup_kernel<<<608, 256>>>(pos, edge, Wq, bq, Wk, bk, Wv, bv,
                                    Wout, bout, gamma, beta);
    edge_kernel<<<(NE * 4 + 255) / 256, 256>>>(edge);
    node_kernel<<<(NN / 2 * 4 + 255) / 256, 256>>>(out);
}

// round 13
// speedup vs baseline: 1.1846x; 1.0615x over previous
#include <cuda_runtime.h>

#define NN 100000   // nodes
#define NPAD 100096 // padded node count
#define NE 500000   // edges
#define NH 4        // heads
#define HD 32       // output width
#define PROJ 128
#define U16 16      // folded edge-feature width

// folded-parameter layout inside g_fold (floats)
#define A_OFF     0            // 4*3*3 = 36  quadratic form (pre-scaled 1/sqrt(32))
#define LIN_OFF   36           // 4*3  = 12
#define S0_OFF    48           // 4
#define SCORE_SZ  52
#define B_OFF     52           // 16*32 = 512
#define BOUT_OFF  564          // 32
#define GAMMA_OFF 596          // 32
#define BETA_OFF  628          // 32
#define FOLD_SZ   660

// ---------------- device scratch (no allocations allowed) ----------------
__device__ __align__(16) float g_seg[NPAD * U16]; // zeroed by pack_setup each launch
__device__ __align__(16) float4 g_pos4[NN];       // padded positions for 1-LDG gathers
__device__ __align__(16) float g_fold[FOLD_SZ];   // folded params
__device__ int   g_is64;                          // edge_index dtype flag

// ---------------- kernel 1: zero seg + pack positions + weight fold ----------------
__global__ void __launch_bounds__(256) pack_setup_kernel(
        const float* __restrict__ pos,
        const int* __restrict__ eraw,
        const float* __restrict__ Wq, const float* __restrict__ bq,
        const float* __restrict__ Wk, const float* __restrict__ bk,
        const float* __restrict__ Wv, const float* __restrict__ bv,
        const float* __restrict__ Wout, const float* __restrict__ bout,
        const float* __restrict__ gamma, const float* __restrict__ beta) {
    const int gid = blockIdx.x * blockDim.x + threadIdx.x;
    const int gsz = gridDim.x * blockDim.x;

    // zero the accumulator (grid-stride, v4) — covers padded rows too
    float4* s4 = reinterpret_cast<float4*>(g_seg);
    const int n4 = NPAD * U16 / 4;
    const float4 z = make_float4(0.f, 0.f, 0.f, 0.f);
    for (int j = gid; j < n4; j += gsz) s4[j] = z;

    // pack positions into float4
    for (int j = gid; j < NN; j += gsz)
        g_pos4[j] = make_float4(__ldg(&pos[j * 3 + 0]),
                                __ldg(&pos[j * 3 + 1]),
                                __ldg(&pos[j * 3 + 2]), 0.f);

    const int t = threadIdx.x;
    const float inv = 0.17677669529663687f;  // 1/sqrt(32)

    if (blockIdx.x < 2) {
        // ---- B fold: one thread per output, lane = o (coalesced Wout rows) ----
        int idx = blockIdx.x * 256 + t;           // 0..511
        int j = idx >> 5, o = idx & 31;
        int h = j >> 2, ii = j & 3;
        const float* wsrc = (ii < 3) ? &Wv[ii * PROJ + h * HD] : &bv[h * HD];
        const float* wo   = &Wout[(size_t)h * HD * HD + o];
        float acc[8];
#pragma unroll
        for (int k = 0; k < 8; k++) acc[k] = 0.f;
#pragma unroll
        for (int d = 0; d < HD; d += 8) {
#pragma unroll
            for (int k = 0; k < 8; k++)
                acc[k] = fmaf(__ldg(&wsrc[d + k]), __ldg(&wo[(d + k) * HD]), acc[k]);
        }
        g_fold[B_OFF + idx] = ((acc[0] + acc[1]) + (acc[2] + acc[3]))
                            + ((acc[4] + acc[5]) + (acc[6] + acc[7]));
    } else if (blockIdx.x == 2) {
        if (t < NH * 9) {
            int h = t / 9, ii = (t % 9) / 3, jj = t % 3;
            const float* wq = &Wq[ii * PROJ + h * HD];
            const float* wk = &Wk[jj * PROJ + h * HD];
            float acc[8];
#pragma unroll
            for (int k = 0; k < 8; k++) acc[k] = 0.f;
#pragma unroll
            for (int d = 0; d < HD; d += 8) {
#pragma unroll
                for (int k = 0; k < 8; k++)
                    acc[k] = fmaf(__ldg(&wq[d + k]), __ldg(&wk[d + k]), acc[k]);
            }
            g_fold[A_OFF + t] = (((acc[0] + acc[1]) + (acc[2] + acc[3]))
                               + ((acc[4] + acc[5]) + (acc[6] + acc[7]))) * inv;
        } else if (t < 48) {
            int idx = t - 36;
            int h = idx / 3, ii = idx % 3;
            const float* wq = &Wq[ii * PROJ + h * HD];
            const float* wk = &Wk[ii * PROJ + h * HD];
            const float* bqv = &bq[h * HD];
            const float* bkv = &bk[h * HD];
            float a0 = 0.f, a1 = 0.f, a2 = 0.f, a3 = 0.f;
#pragma unroll
            for (int d = 0; d < HD; d += 2) {
                a0 = fmaf(__ldg(&wq[d]),     __ldg(&bkv[d]),     a0);
                a1 = fmaf(__ldg(&wk[d]),     __ldg(&bqv[d]),     a1);
                a2 = fmaf(__ldg(&wq[d + 1]), __ldg(&bkv[d + 1]), a2);
                a3 = fmaf(__ldg(&wk[d + 1]), __ldg(&bqv[d + 1]), a3);
            }
            g_fold[LIN_OFF + idx] = ((a0 + a1) + (a2 + a3)) * inv;
        } else if (t < 52) {
            int h = t - 48;
            const float* bqv = &bq[h * HD];
            const float* bkv = &bk[h * HD];
            float a0 = 0.f, a1 = 0.f;
#pragma unroll
            for (int d = 0; d < HD; d += 2) {
                a0 = fmaf(__ldg(&bqv[d]),     __ldg(&bkv[d]),     a0);
                a1 = fmaf(__ldg(&bqv[d + 1]), __ldg(&bkv[d + 1]), a1);
            }
            g_fold[S0_OFF + h] = (a0 + a1) * inv;
        } else if (t >= 64 && t < 160) {
            int idx = t - 64;
            const float* src = (idx < HD) ? &bout[idx]
                             : (idx < 2 * HD) ? &gamma[idx - HD]
                             : &beta[idx - 2 * HD];
            g_fold[BOUT_OFF + idx] = __ldg(src);
        } else if (t == 192) {
            // int64 edge_index: node ids < 1e5 -> every odd 32-bit word is 0.
            int acc = 0;
#pragma unroll
            for (int k = 0; k < 32; k++) acc |= __ldg(&eraw[2 * k + 1]);
            g_is64 = (acc == 0);
        }
    }
}

// ---------------- kernel 2: quad-per-edge scores + scatter (PDL secondary) ----------------
__device__ __forceinline__ void red_add_v4(float* p, float4 v) {
    asm volatile("red.global.add.v4.f32 [%0], {%1,%2,%3,%4};"
                 :: "l"(p), "f"(v.x), "f"(v.y), "f"(v.z), "f"(v.w)
                 : "memory");
}

// NE*4 = 2,000,000 threads; lane quads (aligned) own one edge, lane%4 = head.
__global__ void __launch_bounds__(256) edge_kernel(const int* __restrict__ eraw) {
    __shared__ float sp[SCORE_SZ];

    const int gid = blockIdx.x * blockDim.x + threadIdx.x;
    const int e = gid >> 2;
    const int h = gid & 3;

    // wait for pack_setup's writes (g_fold, g_pos4, g_seg zero, g_is64)
    cudaGridDependencySynchronize();

    if (threadIdx.x < SCORE_SZ) sp[threadIdx.x] = g_fold[threadIdx.x];
    __syncthreads();

    if (e >= NE) return;                   // NE*4 % 32 == 0 -> whole warps drop

    int row, col;
    if (g_is64) {
        const long long* p = reinterpret_cast<const long long*>(eraw);
        row = (int)__ldg(&p[e]);           // quad-same address -> merged
        col = (int)__ldg(&p[NE + e]);
    } else {
        row = __ldg(&eraw[e]);
        col = __ldg(&eraw[NE + e]);
    }

    // all 4 quad lanes load both positions; same-line lanes merge in L1tex
    float4 pr = g_pos4[row];
    float4 pc = g_pos4[col];
    const float r0 = pr.x - pc.x, r1 = pr.y - pc.y, r2 = pr.z - pc.z;

    // this lane's head score (folded quadratic form)
    const float* A = &sp[A_OFF + h * 9];
    float t0 = sp[LIN_OFF + h * 3 + 0];
    t0 = fmaf(A[0], r0, fmaf(A[1], r1, fmaf(A[2], r2, t0)));
    float t1 = sp[LIN_OFF + h * 3 + 1];
    t1 = fmaf(A[3], r0, fmaf(A[4], r1, fmaf(A[5], r2, t1)));
    float t2 = sp[LIN_OFF + h * 3 + 2];
    t2 = fmaf(A[6], r0, fmaf(A[7], r1, fmaf(A[8], r2, t2)));
    float s = fmaf(r0, t0, fmaf(r1, t1, fmaf(r2, t2, sp[S0_OFF + h])));

    // quad softmax (laneMask 1,2 stay inside aligned quads)
    const unsigned mask = 0xffffffffu;
    float mx = s;
    mx = fmaxf(mx, __shfl_xor_sync(mask, mx, 1));
    mx = fmaxf(mx, __shfl_xor_sync(mask, mx, 2));
    float a = __expf(s - mx);
    float den = a;
    den += __shfl_xor_sync(mask, den, 1);
    den += __shfl_xor_sync(mask, den, 2);
    float ah = a / den;

    // one red.v4 per lane; quad covers one contiguous 64B block of g_seg[col]
    red_add_v4(&g_seg[(size_t)col * U16 + h * 4],
               make_float4(ah * r0, ah * r1, ah * r2, ah));
}

// ---------------- kernel 3: per-node u@B + LN + SiLU (PDL secondary) ----------------
__global__ void __launch_bounds__(256) node_kernel(float* __restrict__ out) {
    __shared__ __align__(16) float sB[U16 * HD];   // 512 floats
    __shared__ __align__(16) float sEpi[3 * HD];   // bout | gamma | beta

    // preamble: stage folded params (written by pack_setup, which fully completed
    // before edge_kernel's gridsync released; edge never writes g_fold) — overlaps
    // edge_kernel's tail.
    for (int i = threadIdx.x; i < U16 * HD; i += 256) sB[i] = g_fold[B_OFF + i];
    for (int i = threadIdx.x; i < 3 * HD; i += 256)  sEpi[i] = g_fold[BOUT_OFF + i];
    __syncthreads();

    // wait for edge_kernel's scatter into g_seg
    cudaGridDependencySynchronize();

    int gt   = blockIdx.x * blockDim.x + threadIdx.x;
    int pair = gt >> 2;
    int sub  = gt & 3;
    int n0   = pair * 2;          // NN is even -> n0, n0+1 both valid when n0 < NN
    bool valid = (n0 < NN);
    unsigned mask = 0xffffffffu;

    float s0[U16], s1[U16];
    if (valid) {
        const float4* p0 = reinterpret_cast<const float4*>(&g_seg[(size_t)n0 * U16]);
        const float4* p1 = reinterpret_cast<const float4*>(&g_seg[(size_t)(n0 + 1) * U16]);
#pragma unroll
        for (int k = 0; k < 4; k++) {
            float4 v = p0[k];
            s0[k*4+0]=v.x; s0[k*4+1]=v.y; s0[k*4+2]=v.z; s0[k*4+3]=v.w;
        }
#pragma unroll
        for (int k = 0; k < 4; k++) {
            float4 v = p1[k];
            s1[k*4+0]=v.x; s1[k*4+1]=v.y; s1[k*4+2]=v.z; s1[k*4+3]=v.w;
        }
    } else {
#pragma unroll
        for (int k = 0; k < U16; k++) { s0[k] = 0.f; s1[k] = 0.f; }
    }

    float rinv0 = 1.0f / fmaxf(s0[3] + s0[7] + s0[11] + s0[15], 1.0f);
    float rinv1 = 1.0f / fmaxf(s1[3] + s1[7] + s1[11] + s1[15], 1.0f);

    const int o0 = sub * 8;
    float y0[8], y1[8];
#pragma unroll
    for (int c = 0; c < 8; c++) { y0[c] = 0.f; y1[c] = 0.f; }
#pragma unroll
    for (int j = 0; j < U16; j++) {
        const float4* brow = reinterpret_cast<const float4*>(&sB[j * HD + o0]);
        float4 b0 = brow[0], b1 = brow[1];
        float a0 = s0[j], a1 = s1[j];
        y0[0]=fmaf(a0,b0.x,y0[0]); y0[1]=fmaf(a0,b0.y,y0[1]);
        y0[2]=fmaf(a0,b0.z,y0[2]); y0[3]=fmaf(a0,b0.w,y0[3]);
        y0[4]=fmaf(a0,b1.x,y0[4]); y0[5]=fmaf(a0,b1.y,y0[5]);
        y0[6]=fmaf(a0,b1.z,y0[6]); y0[7]=fmaf(a0,b1.w,y0[7]);
        y1[0]=fmaf(a1,b0.x,y1[0]); y1[1]=fmaf(a1,b0.y,y1[1]);
        y1[2]=fmaf(a1,b0.z,y1[2]); y1[3]=fmaf(a1,b0.w,y1[3]);
        y1[4]=fmaf(a1,b1.x,y1[4]); y1[5]=fmaf(a1,b1.y,y1[5]);
        y1[6]=fmaf(a1,b1.z,y1[6]); y1[7]=fmaf(a1,b1.w,y1[7]);
    }

    float sum0 = 0.f, sum1 = 0.f;
#pragma unroll
    for (int c = 0; c < 8; c++) {
        y0[c] = fmaf(y0[c], rinv0, sEpi[o0 + c]);
        y1[c] = fmaf(y1[c], rinv1, sEpi[o0 + c]);
        sum0 += y0[c]; sum1 += y1[c];
    }
    sum0 += __shfl_xor_sync(mask, sum0, 1);
    sum0 += __shfl_xor_sync(mask, sum0, 2);
    sum1 += __shfl_xor_sync(mask, sum1, 1);
    sum1 += __shfl_xor_sync(mask, sum1, 2);
    float mu0 = sum0 * (1.0f / 32.0f);
    float mu1 = sum1 * (1.0f / 32.0f);

    float sq0 = 0.f, sq1 = 0.f;
#pragma unroll
    for (int c = 0; c < 8; c++) {
        float d0 = y0[c] - mu0; sq0 = fmaf(d0, d0, sq0);
        float d1 = y1[c] - mu1; sq1 = fmaf(d1, d1, sq1);
    }
    sq0 += __shfl_xor_sync(mask, sq0, 1);
    sq0 += __shfl_xor_sync(mask, sq0, 2);
    sq1 += __shfl_xor_sync(mask, sq1, 1);
    sq1 += __shfl_xor_sync(mask, sq1, 2);
    float sf0 = rsqrtf(sq0 * (1.0f / 32.0f) + 1e-5f);
    float sf1 = rsqrtf(sq1 * (1.0f / 32.0f) + 1e-5f);

    if (!valid) return;

    float4* op0 = reinterpret_cast<float4*>(&out[(size_t)n0 * HD + o0]);
    float4* op1 = reinterpret_cast<float4*>(&out[(size_t)(n0 + 1) * HD + o0]);
#pragma unroll
    for (int k = 0; k < 2; k++) {
        float4 v0, v1;
        float* vp0 = &v0.x;
        float* vp1 = &v1.x;
#pragma unroll
        for (int c = 0; c < 4; c++) {
            int o = o0 + k * 4 + c;
            float g = sEpi[HD + o], bt = sEpi[2 * HD + o];
            float x0 = (y0[k*4+c] - mu0) * sf0 * g + bt;
            float x1 = (y1[k*4+c] - mu1) * sf1 * g + bt;
            vp0[c] = x0 / (1.0f + __expf(-x0));
            vp1[c] = x1 / (1.0f + __expf(-x1));
        }
        op0[k] = v0;
        op1[k] = v1;
    }
}

// ---------------- launch ----------------
extern "C" void kernel_launch(void* const* d_in, const int* in_sizes, int n_in,
                              void* d_out, int out_size) {
    const float* pos   = (const float*)d_in[0];
    const int*   edge  = (const int*)d_in[1];
    const float* Wq    = (const float*)d_in[2];
    const float* bq    = (const float*)d_in[3];
    const float* Wk    = (const float*)d_in[4];
    const float* bk    = (const float*)d_in[5];
    const float* Wv    = (const float*)d_in[6];
    const float* bv    = (const float*)d_in[7];
    const float* Wout  = (const float*)d_in[8];
    const float* bout  = (const float*)d_in[9];
    const float* gamma = (const float*)d_in[10];
    const float* beta  = (const float*)d_in[11];
    float* out = (float*)d_out;

    pack_setup_kernel<<<608, 256>>>(pos, edge, Wq, bq, Wk, bk, Wv, bv,
                                    Wout, bout, gamma, beta);

    // PDL: edge overlaps pack's tail; node overlaps edge's tail.
    cudaLaunchAttribute pdl[1];
    pdl[0].id = cudaLaunchAttributeProgrammaticStreamSerialization;
    pdl[0].val.programmaticStreamSerializationAllowed = 1;

    {
        cudaLaunchConfig_t cfg = {};
        cfg.gridDim  = dim3((NE * 4 + 255) / 256, 1, 1);
        cfg.blockDim = dim3(256, 1, 1);
        cfg.attrs = pdl;
        cfg.numAttrs = 1;
        cudaLaunchKernelEx(&cfg, edge_kernel, edge);
    }
    {
        cudaLaunchConfig_t cfg = {};
        cfg.gridDim  = dim3((NN / 2 * 4 + 255) / 256, 1, 1);
        cfg.blockDim = dim3(256, 1, 1);
        cfg.attrs = pdl;
        cfg.numAttrs = 1;
        cudaLaunchKernelEx(&cfg, node_kernel, out);
    }
}